// round 4
// baseline (speedup 1.0000x reference)
#include <cuda_runtime.h>
#include <math.h>

#define A_COUNT 1024
#define DFEAT   128
#define NTOTAL  524288

// eps = 1e-4 / D
#define EPS (7.8125e-7f)

// rows per warp
#define RPW 8
#define BLOCK_THREADS 256
#define WARPS_PER_BLOCK (BLOCK_THREADS / 32)
#define ROWS_PER_BLOCK (WARPS_PER_BLOCK * RPW)   // 64
#define GRID_BLOCKS (NTOTAL / ROWS_PER_BLOCK)    // 8192

// Zero at module load; the last finishing block resets them after use, so
// every graph replay (and the first correctness call) starts from zeros.
__device__ float        g_per_anchor[A_COUNT];
__device__ unsigned int g_done;

__global__ __launch_bounds__(BLOCK_THREADS)
void dist_kernel(const float* __restrict__ anchors,
                 const float* __restrict__ X,
                 const int*   __restrict__ seg,
                 float*       __restrict__ out) {
    const int lane = threadIdx.x & 31;
    const int warp = threadIdx.x >> 5;
    const int base = (blockIdx.x * WARPS_PER_BLOCK + warp) * RPW;

    // Per-lane float4 covers the whole 128-float row: lane*4 .. lane*4+3.
    const float4* __restrict__ X4 = reinterpret_cast<const float4*>(X);
    const float4* __restrict__ A4 = reinterpret_cast<const float4*>(anchors);

    int   cur_seg = seg[base];
    float4 a = A4[(size_t)cur_seg * (DFEAT / 4) + lane];
    float4 x = X4[(size_t)base * (DFEAT / 4) + lane];

    float acc = 0.0f;   // only lane 0's value matters

    #pragma unroll
    for (int r = 0; r < RPW; r++) {
        const int row = base + r;

        // Prefetch next row's data before consuming current (MLP>=2 per warp,
        // interleaved — keep MLP_p1 low to avoid L1tex-queue spread).
        float4 x_next;
        int    s_next = cur_seg;
        if (r + 1 < RPW) {
            s_next = seg[row + 1];
            x_next = X4[(size_t)(row + 1) * (DFEAT / 4) + lane];
        }

        float d0 = x.x - a.x;
        float d1 = x.y - a.y;
        float d2 = x.z - a.z;
        float d3 = x.w - a.w;
        float ss = d0 * d0 + d1 * d1 + d2 * d2 + d3 * d3;

        #pragma unroll
        for (int off = 16; off; off >>= 1)
            ss += __shfl_xor_sync(0xffffffffu, ss, off);

        if (lane == 0) acc += sqrtf(ss + EPS);

        if (r + 1 < RPW) {
            if (s_next != cur_seg) {
                // Segment boundary (warp-uniform): flush and reload anchor.
                if (lane == 0) {
                    atomicAdd(&g_per_anchor[cur_seg], acc);
                    acc = 0.0f;
                }
                cur_seg = s_next;
                a = A4[(size_t)cur_seg * (DFEAT / 4) + lane];
            }
            x = x_next;
        }
    }

    if (lane == 0) atomicAdd(&g_per_anchor[cur_seg], acc);

    // ---- fused finalize: last block to finish does the log1p reduction ----
    __shared__ bool is_last;
    __shared__ float sdata[WARPS_PER_BLOCK];
    if (threadIdx.x == 0) {
        __threadfence();                       // publish this block's atomics
        unsigned t = atomicAdd(&g_done, 1u);
        is_last = (t == GRID_BLOCKS - 1);
    }
    __syncthreads();
    if (!is_last) return;

    __threadfence();                           // acquire: see all blocks' sums

    // 256 threads, 4 anchors each.
    float v = 0.0f;
    #pragma unroll
    for (int k = 0; k < A_COUNT / BLOCK_THREADS; k++) {
        const int idx = threadIdx.x + k * BLOCK_THREADS;
        v += log1pf(__ldcg(&g_per_anchor[idx]));
        g_per_anchor[idx] = 0.0f;              // reset for next replay
    }

    #pragma unroll
    for (int off = 16; off; off >>= 1)
        v += __shfl_xor_sync(0xffffffffu, v, off);
    if (lane == 0) sdata[warp] = v;
    __syncthreads();

    if (threadIdx.x == 0) {
        float w = 0.0f;
        #pragma unroll
        for (int i = 0; i < WARPS_PER_BLOCK; i++) w += sdata[i];
        out[0] = w / (float)NTOTAL;
        g_done = 0u;                           // reset counter for next replay
    }
}

extern "C" void kernel_launch(void* const* d_in, const int* in_sizes, int n_in,
                              void* d_out, int out_size) {
    const float* anchors = (const float*)d_in[0];   // [A, D]
    const float* Xn_flat = (const float*)d_in[1];   // [TOTAL, D]
    const int*   seg     = (const int*)d_in[2];     // [TOTAL]
    float* out = (float*)d_out;

    dist_kernel<<<GRID_BLOCKS, BLOCK_THREADS>>>(anchors, Xn_flat, seg, out);
}

// round 6
// speedup vs baseline: 1.0204x; 1.0204x over previous
#include <cuda_runtime.h>
#include <math.h>

#define A_COUNT 1024
#define DFEAT   128
#define NTOTAL  524288

// eps = 1e-4 / D
#define EPS (7.8125e-7f)

// 8 lanes per row; 4 rows per warp-iteration; 4 iterations -> 16 rows/warp.
#define ITERS 4
#define ROWS_PER_WARP (ITERS * 4)                  // 16
#define BLOCK_THREADS 256
#define WARPS_PER_BLOCK (BLOCK_THREADS / 32)
#define ROWS_PER_BLOCK (WARPS_PER_BLOCK * ROWS_PER_WARP)  // 128
#define GRID_BLOCKS (NTOTAL / ROWS_PER_BLOCK)      // 4096

// Zero at module load; finalize_kernel resets it after reading, so every
// graph replay (and the first correctness call) sees zeros. No init kernel.
__device__ float g_per_anchor[A_COUNT];

__global__ __launch_bounds__(BLOCK_THREADS)
void dist_kernel(const float* __restrict__ anchors,
                 const float* __restrict__ X,
                 const int*   __restrict__ seg) {
    const int lane = threadIdx.x & 31;
    const int warp = threadIdx.x >> 5;
    const int li   = lane & 7;        // lane within 8-lane row group
    const int base = (blockIdx.x * WARPS_PER_BLOCK + warp) * ROWS_PER_WARP;
    const int g    = lane >> 3;       // row group 0..3

    const float4* __restrict__ X4 = reinterpret_cast<const float4*>(X);
    const float4* __restrict__ A4 = reinterpret_cast<const float4*>(anchors);

    // Iteration i: this group handles row base + 4*i + g.
    int row = base + g;
    int cur_seg = seg[row];

    // Anchor chunks for this lane: float4 indices li, li+8, li+16, li+24.
    float4 a[4];
    #pragma unroll
    for (int k = 0; k < 4; k++)
        a[k] = A4[(size_t)cur_seg * (DFEAT / 4) + li + 8 * k];

    // Current row data (4 LDG.128, each warp-coalesced to 4 cache lines).
    float4 x[4];
    #pragma unroll
    for (int k = 0; k < 4; k++)
        x[k] = X4[(size_t)row * (DFEAT / 4) + li + 8 * k];

    float acc = 0.0f;   // per-group leader (li==0) running segment sum

    #pragma unroll
    for (int i = 0; i < ITERS; i++) {
        // Prefetch next iteration's row before consuming current.
        float4 xn[4];
        int s_next = cur_seg;
        if (i + 1 < ITERS) {
            const int nrow = base + 4 * (i + 1) + g;
            s_next = seg[nrow];
            #pragma unroll
            for (int k = 0; k < 4; k++)
                xn[k] = X4[(size_t)nrow * (DFEAT / 4) + li + 8 * k];
        }

        // Lane-local partial over its 16 floats.
        float ss = 0.0f;
        #pragma unroll
        for (int k = 0; k < 4; k++) {
            float d0 = x[k].x - a[k].x;
            float d1 = x[k].y - a[k].y;
            float d2 = x[k].z - a[k].z;
            float d3 = x[k].w - a[k].w;
            ss += d0 * d0 + d1 * d1 + d2 * d2 + d3 * d3;
        }

        // 3-step butterfly within the 8-lane group: reduces 4 rows at once.
        #pragma unroll
        for (int off = 4; off; off >>= 1)
            ss += __shfl_xor_sync(0xffffffffu, ss, off);

        if (li == 0) acc += sqrtf(ss + EPS);

        if (i + 1 < ITERS) {
            if (s_next != cur_seg) {
                // Per-group segment boundary: flush and reload anchor.
                if (li == 0) {
                    atomicAdd(&g_per_anchor[cur_seg], acc);
                    acc = 0.0f;
                }
                cur_seg = s_next;
                #pragma unroll
                for (int k = 0; k < 4; k++)
                    a[k] = A4[(size_t)cur_seg * (DFEAT / 4) + li + 8 * k];
            }
            #pragma unroll
            for (int k = 0; k < 4; k++) x[k] = xn[k];
        }
    }

    if (li == 0) atomicAdd(&g_per_anchor[cur_seg], acc);
}

__global__ __launch_bounds__(1024)
void finalize_kernel(float* __restrict__ out) {
    __shared__ float sdata[32];
    const int tid = threadIdx.x;     // 1024 threads, one per anchor

    float pa = g_per_anchor[tid];
    g_per_anchor[tid] = 0.0f;        // reset for the next graph replay

    float v = log1pf(pa);

    #pragma unroll
    for (int off = 16; off; off >>= 1)
        v += __shfl_xor_sync(0xffffffffu, v, off);

    if ((tid & 31) == 0) sdata[tid >> 5] = v;
    __syncthreads();

    if (tid < 32) {
        float w = sdata[tid];
        #pragma unroll
        for (int off = 16; off; off >>= 1)
            w += __shfl_xor_sync(0xffffffffu, w, off);
        if (tid == 0) out[0] = w / (float)NTOTAL;
    }
}

extern "C" void kernel_launch(void* const* d_in, const int* in_sizes, int n_in,
                              void* d_out, int out_size) {
    const float* anchors = (const float*)d_in[0];   // [A, D]
    const float* Xn_flat = (const float*)d_in[1];   // [TOTAL, D]
    const int*   seg     = (const int*)d_in[2];     // [TOTAL]
    float* out = (float*)d_out;

    dist_kernel<<<GRID_BLOCKS, BLOCK_THREADS>>>(anchors, Xn_flat, seg);

    finalize_kernel<<<1, 1024>>>(out);
}